// round 4
// baseline (speedup 1.0000x reference)
#include <cuda_runtime.h>
#include <math.h>

#define D     256
#define N1C   40000
#define N2C   8000

// ---------------- scratch (no cudaMalloc allowed) ----------------
__device__ float g_agg1[(size_t)N1C * D];   // 40.96 MB
__device__ float g_cnt1[N1C];
__device__ float g_inv1[N1C];
__device__ float g_h1[(size_t)N1C * D];     // 40.96 MB
__device__ float g_agg2[(size_t)N2C * D];   // 8.19 MB
__device__ float g_cnt2[N2C];
__device__ float g_inv2[N2C];
__device__ float g_Wt1[512 * D];            // [Wl^T ; Wr^T] K-major
__device__ float g_Wt2[512 * D];

// ---------------- weight transpose: Wt[k][n] = (k<256 ? Wl[n][k] : Wr[n][k-256])
__global__ void prep_w_kernel(const float* __restrict__ Wl,
                              const float* __restrict__ Wr,
                              float* __restrict__ Wt) {
    int i = blockIdx.x * blockDim.x + threadIdx.x;
    if (i >= 512 * D) return;
    int k = i / D, n = i % D;
    Wt[i] = (k < D) ? Wl[n * D + k] : Wr[n * D + (k - D)];
}

// vectorized no-return global reduction (PTX ISA 8.1, sm_90+)
__device__ __forceinline__ void red_add_v4(float* addr, float4 v) {
    asm volatile("red.global.add.v4.f32 [%0], {%1,%2,%3,%4};"
                 :: "l"(addr), "f"(v.x), "f"(v.y), "f"(v.z), "f"(v.w)
                 : "memory");
}

// ---------------- edge scatter: one warp per edge, 256 floats/edge ----------------
__global__ void scatter_kernel(const float* __restrict__ x,
                               const int* __restrict__ src,
                               const int* __restrict__ dst, int E,
                               float* __restrict__ agg, float* __restrict__ cnt) {
    int e = (blockIdx.x * blockDim.x + threadIdx.x) >> 5;
    int lane = threadIdx.x & 31;
    if (e >= E) return;
    int s = src[e];
    int d = dst[e];
    const float4* xs = (const float4*)(x + (size_t)s * D);
    float* ag = agg + (size_t)d * D;
    float4 v0 = __ldg(xs + lane);
    float4 v1 = __ldg(xs + lane + 32);
    red_add_v4(ag + lane * 4, v0);
    red_add_v4(ag + (lane + 32) * 4, v1);
    if (lane == 0) atomicAdd(cnt + d, 1.0f);
}

__global__ void inv_kernel(const float* __restrict__ cnt, float* __restrict__ inv, int n) {
    int i = blockIdx.x * blockDim.x + threadIdx.x;
    if (i < n) inv[i] = 1.0f / fmaxf(cnt[i], 1.0f);
}

// ---------------- fused SAGE GEMM ----------------
// out[M,256] = tanh( [agg*inv | xt] (M x 512) @ Wt (512 x 256) + bias )
// 128x128 tile, BK=16, 256 threads, 8x8 micro-tile per thread.
__global__ __launch_bounds__(256, 2)
void sage_gemm_kernel(const float* __restrict__ agg, const float* __restrict__ inv,
                      const float* __restrict__ xt,  const float* __restrict__ Wt,
                      const float* __restrict__ bias, float* __restrict__ out, int M) {
    __shared__ float sA[16 * 128];   // transposed: sA[k][row]
    __shared__ float sB[16 * 128];   // sB[k][col]

    const int tid = threadIdx.x;
    const int tx = tid & 15;         // 16 col groups
    const int ty = tid >> 4;         // 16 row groups
    const int row0 = blockIdx.x * 128;
    const int col0 = blockIdx.y * 128;

    // A load mapping: thread -> row = tid/2, two float4 at kq in {2*(tid&1), 2*(tid&1)+1}
    const int a_row  = tid >> 1;
    const int a_kq0  = (tid & 1) * 2;
    // B load mapping: thread -> k = tid/16, two float4 at n4 in {2*(tid&15), +1}
    const int b_k    = tid >> 4;
    const int b_n40  = (tid & 15) * 2;

    const int rowg = row0 + a_row;
    const bool rvalid = rowg < M;
    const float invv = rvalid ? inv[rowg] : 0.0f;
    const float* aggrow = agg + (size_t)rowg * D;
    const float* xrow   = xt  + (size_t)rowg * D;

    float acc[8][8];
    #pragma unroll
    for (int i = 0; i < 8; i++)
        #pragma unroll
        for (int j = 0; j < 8; j++) acc[i][j] = 0.0f;

    #pragma unroll 1
    for (int kt = 0; kt < 32; kt++) {             // K = 512, BK = 16
        const int kbase = kt * 16;
        const bool firstHalf = (kbase < D);
        const float* srcrow = firstHalf ? aggrow : xrow;
        const int koff = firstHalf ? kbase : (kbase - D);
        const float scale = firstHalf ? invv : 1.0f;

        // load A tile (scaled on the fly), store transposed
        #pragma unroll
        for (int j = 0; j < 2; j++) {
            const int kq = a_kq0 + j;
            float4 v = make_float4(0.f, 0.f, 0.f, 0.f);
            if (rvalid) v = *(const float4*)(srcrow + koff + kq * 4);
            v.x *= scale; v.y *= scale; v.z *= scale; v.w *= scale;
            sA[(kq * 4 + 0) * 128 + a_row] = v.x;
            sA[(kq * 4 + 1) * 128 + a_row] = v.y;
            sA[(kq * 4 + 2) * 128 + a_row] = v.z;
            sA[(kq * 4 + 3) * 128 + a_row] = v.w;
        }
        // load B tile
        #pragma unroll
        for (int j = 0; j < 2; j++) {
            const int n4 = b_n40 + j;
            float4 w = *(const float4*)(Wt + (size_t)(kbase + b_k) * D + col0 + n4 * 4);
            *(float4*)(sB + b_k * 128 + n4 * 4) = w;
        }
        __syncthreads();

        #pragma unroll
        for (int k = 0; k < 16; k++) {
            float a[8], b[8];
            *(float4*)(a)     = *(const float4*)(sA + k * 128 + ty * 8);
            *(float4*)(a + 4) = *(const float4*)(sA + k * 128 + ty * 8 + 4);
            *(float4*)(b)     = *(const float4*)(sB + k * 128 + tx * 8);
            *(float4*)(b + 4) = *(const float4*)(sB + k * 128 + tx * 8 + 4);
            #pragma unroll
            for (int i = 0; i < 8; i++)
                #pragma unroll
                for (int j = 0; j < 8; j++)
                    acc[i][j] = fmaf(a[i], b[j], acc[i][j]);
        }
        __syncthreads();
    }

    // epilogue: bias + tanh
    float bs[8];
    *(float4*)(bs)     = *(const float4*)(bias + col0 + tx * 8);
    *(float4*)(bs + 4) = *(const float4*)(bias + col0 + tx * 8 + 4);

    #pragma unroll
    for (int i = 0; i < 8; i++) {
        const int r = row0 + ty * 8 + i;
        if (r >= M) continue;
        float4 o0, o1;
        o0.x = tanhf(acc[i][0] + bs[0]);
        o0.y = tanhf(acc[i][1] + bs[1]);
        o0.z = tanhf(acc[i][2] + bs[2]);
        o0.w = tanhf(acc[i][3] + bs[3]);
        o1.x = tanhf(acc[i][4] + bs[4]);
        o1.y = tanhf(acc[i][5] + bs[5]);
        o1.z = tanhf(acc[i][6] + bs[6]);
        o1.w = tanhf(acc[i][7] + bs[7]);
        float* orow = out + (size_t)r * D + col0 + tx * 8;
        *(float4*)(orow)     = o0;
        *(float4*)(orow + 4) = o1;
    }
}

// ---------------- launch ----------------
extern "C" void kernel_launch(void* const* d_in, const int* in_sizes, int n_in,
                              void* d_out, int out_size) {
    const float* nodes = (const float*)d_in[0];
    const float* Wl1   = (const float*)d_in[1];
    const float* b1    = (const float*)d_in[2];
    const float* Wr1   = (const float*)d_in[3];
    const float* Wl2   = (const float*)d_in[4];
    const float* b2    = (const float*)d_in[5];
    const float* Wr2   = (const float*)d_in[6];
    const int*   src1  = (const int*)d_in[7];
    const int*   dst1  = (const int*)d_in[8];
    const int*   src2  = (const int*)d_in[9];
    const int*   dst2  = (const int*)d_in[10];
    const int E1 = in_sizes[7];
    const int E2 = in_sizes[9];

    float *p_agg1, *p_cnt1, *p_inv1, *p_h1, *p_agg2, *p_cnt2, *p_inv2, *p_Wt1, *p_Wt2;
    cudaGetSymbolAddress((void**)&p_agg1, g_agg1);
    cudaGetSymbolAddress((void**)&p_cnt1, g_cnt1);
    cudaGetSymbolAddress((void**)&p_inv1, g_inv1);
    cudaGetSymbolAddress((void**)&p_h1,   g_h1);
    cudaGetSymbolAddress((void**)&p_agg2, g_agg2);
    cudaGetSymbolAddress((void**)&p_cnt2, g_cnt2);
    cudaGetSymbolAddress((void**)&p_inv2, g_inv2);
    cudaGetSymbolAddress((void**)&p_Wt1,  g_Wt1);
    cudaGetSymbolAddress((void**)&p_Wt2,  g_Wt2);

    cudaMemsetAsync(p_agg1, 0, sizeof(float) * (size_t)N1C * D);
    cudaMemsetAsync(p_cnt1, 0, sizeof(float) * N1C);
    cudaMemsetAsync(p_agg2, 0, sizeof(float) * (size_t)N2C * D);
    cudaMemsetAsync(p_cnt2, 0, sizeof(float) * N2C);

    prep_w_kernel<<<(512 * D) / 256, 256>>>(Wl1, Wr1, p_Wt1);
    prep_w_kernel<<<(512 * D) / 256, 256>>>(Wl2, Wr2, p_Wt2);

    // layer 1
    {
        long long threads = (long long)E1 * 32;
        int blocks = (int)((threads + 255) / 256);
        scatter_kernel<<<blocks, 256>>>(nodes, src1, dst1, E1, p_agg1, p_cnt1);
    }
    inv_kernel<<<(N1C + 255) / 256, 256>>>(p_cnt1, p_inv1, N1C);
    {
        dim3 grid((N1C + 127) / 128, 2);
        sage_gemm_kernel<<<grid, 256>>>(p_agg1, p_inv1, nodes, p_Wt1, b1, p_h1, N1C);
    }

    // layer 2
    {
        long long threads = (long long)E2 * 32;
        int blocks = (int)((threads + 255) / 256);
        scatter_kernel<<<blocks, 256>>>(p_h1, src2, dst2, E2, p_agg2, p_cnt2);
    }
    inv_kernel<<<(N2C + 255) / 256, 256>>>(p_cnt2, p_inv2, N2C);
    {
        dim3 grid((N2C + 127) / 128, 2);
        sage_gemm_kernel<<<grid, 256>>>(p_agg2, p_inv2, p_h1, p_Wt2, b2,
                                        (float*)d_out, N2C);
    }
}

// round 7
// speedup vs baseline: 1.4415x; 1.4415x over previous
#include <cuda_runtime.h>
#include <cuda_bf16.h>
#include <math.h>
#include <stdint.h>

#define D      256
#define N1C    40000
#define N2C    8000
#define KEXP   1536          // expanded K:  [Ah|Ah|Al] x [Wh;Wl;Wh]
#define KSTORE 1024          // Aexp stored dedup'd: [Ah|Al]
#define BM     128
#define BN     128
#define KC     64            // bf16 per K-chunk (128 B rows, SW128)
#define NCHUNK 24            // 1536/64
#define STAGES 3
#define STAGE_BYTES (BM*128 + BN*128)     // 16 KB A + 16 KB B = 32768
#define SMEM_BYTES  (STAGES*STAGE_BYTES + 1024)

// ---------------- scratch (no cudaMalloc allowed) ----------------
__device__ float g_agg1[(size_t)N1C * D];
__device__ float g_cnt1[N1C];
__device__ float g_inv1[N1C];
__device__ float g_h1[(size_t)N1C * D];
__device__ float g_agg2[(size_t)N2C * D];
__device__ float g_cnt2[N2C];
__device__ float g_inv2[N2C];
__device__ __nv_bfloat16 g_Aexp[(size_t)N1C * KSTORE];   // 81.9 MB (reused layer 2)
__device__ __nv_bfloat16 g_Wb1[(size_t)D * KEXP];         // 768 KB
__device__ __nv_bfloat16 g_Wb2[(size_t)D * KEXP];

// ---------------- helpers ----------------
__device__ __forceinline__ uint32_t smem_u32(const void* p) {
    uint32_t a;
    asm("{ .reg .u64 t; cvta.to.shared.u64 t, %1; cvt.u32.u64 %0, t; }"
        : "=r"(a) : "l"(p));
    return a;
}
#define SWZ(o) ((o) ^ (((o) >> 3) & 0x70))

__device__ __forceinline__ void cp_async16(uint32_t dst, const void* src) {
    asm volatile("cp.async.cg.shared.global [%0], [%1], 16;" :: "r"(dst), "l"(src));
}
#define CP_COMMIT()  asm volatile("cp.async.commit_group;")
#define CP_WAIT(n)   asm volatile("cp.async.wait_group %0;" :: "n"(n))

__device__ __forceinline__ void ldsm_x4(uint32_t& r0, uint32_t& r1,
                                        uint32_t& r2, uint32_t& r3, uint32_t addr) {
    asm volatile("ldmatrix.sync.aligned.m8n8.x4.shared.b16 {%0,%1,%2,%3}, [%4];"
                 : "=r"(r0), "=r"(r1), "=r"(r2), "=r"(r3) : "r"(addr));
}
__device__ __forceinline__ void mma_bf16(float* c,
        uint32_t a0, uint32_t a1, uint32_t a2, uint32_t a3,
        uint32_t b0, uint32_t b1) {
    asm volatile(
        "mma.sync.aligned.m16n8k16.row.col.f32.bf16.bf16.f32 "
        "{%0,%1,%2,%3}, {%4,%5,%6,%7}, {%8,%9}, {%0,%1,%2,%3};"
        : "+f"(c[0]), "+f"(c[1]), "+f"(c[2]), "+f"(c[3])
        : "r"(a0), "r"(a1), "r"(a2), "r"(a3), "r"(b0), "r"(b1));
}

// ---------------- edge scatter (R4-proven) ----------------
__device__ __forceinline__ void red_add_v4(float* addr, float4 v) {
    asm volatile("red.global.add.v4.f32 [%0], {%1,%2,%3,%4};"
                 :: "l"(addr), "f"(v.x), "f"(v.y), "f"(v.z), "f"(v.w) : "memory");
}
__global__ void scatter_kernel(const float* __restrict__ x,
                               const int* __restrict__ src,
                               const int* __restrict__ dst, int E,
                               float* __restrict__ agg, float* __restrict__ cnt) {
    int e = (blockIdx.x * blockDim.x + threadIdx.x) >> 5;
    int lane = threadIdx.x & 31;
    if (e >= E) return;
    int s = src[e];
    int d = dst[e];
    const float4* xs = (const float4*)(x + (size_t)s * D);
    float* ag = agg + (size_t)d * D;
    float4 v0 = __ldg(xs + lane);
    float4 v1 = __ldg(xs + lane + 32);
    red_add_v4(ag + lane * 4, v0);
    red_add_v4(ag + (lane + 32) * 4, v1);
    if (lane == 0) atomicAdd(cnt + d, 1.0f);
}
__global__ void inv_kernel(const float* __restrict__ cnt, float* __restrict__ inv, int n) {
    int i = blockIdx.x * blockDim.x + threadIdx.x;
    if (i < n) inv[i] = 1.0f / fmaxf(cnt[i], 1.0f);
}

// ---------------- weight prep: Wb[n, 0:512]=hi(W), [512:1024]=lo(W), [1024:1536]=hi(W)
__global__ void wprep_kernel(const float* __restrict__ Wl, const float* __restrict__ Wr,
                             __nv_bfloat16* __restrict__ Wb) {
    int i = blockIdx.x * blockDim.x + threadIdx.x;
    if (i >= D * 512) return;
    int n = i / 512, k = i % 512;
    float w = (k < D) ? Wl[n * D + k] : Wr[n * D + (k - D)];
    __nv_bfloat16 hi = __float2bfloat16(w);
    __nv_bfloat16 lo = __float2bfloat16(w - __bfloat162float(hi));
    __nv_bfloat16* row = Wb + (size_t)n * KEXP;
    row[k]        = hi;
    row[512 + k]  = lo;
    row[1024 + k] = hi;
}

// ---------------- A prep: Aexp[m, 0:512]=hi(A), [512:1024]=lo(A); A=[agg*inv | x]
__global__ void aprep_kernel(const float* __restrict__ agg, const float* __restrict__ inv,
                             const float* __restrict__ x, __nv_bfloat16* __restrict__ Aexp,
                             int M) {
    int i = blockIdx.x * blockDim.x + threadIdx.x;
    if (i >= M * 128) return;
    int m  = i >> 7;
    int j4 = (i & 127) * 4;
    float4 v;
    if (j4 < D) {
        v = *(const float4*)(agg + (size_t)m * D + j4);
        float s = inv[m];
        v.x *= s; v.y *= s; v.z *= s; v.w *= s;
    } else {
        v = *(const float4*)(x + (size_t)m * D + (j4 - D));
    }
    float fs[4] = {v.x, v.y, v.z, v.w};
    ushort4 hi4, lo4;
    unsigned short* hp = &hi4.x;
    unsigned short* lp = &lo4.x;
    #pragma unroll
    for (int t = 0; t < 4; t++) {
        __nv_bfloat16 h = __float2bfloat16(fs[t]);
        __nv_bfloat16 l = __float2bfloat16(fs[t] - __bfloat162float(h));
        hp[t] = *(unsigned short*)&h;
        lp[t] = *(unsigned short*)&l;
    }
    __nv_bfloat16* row = Aexp + (size_t)m * KSTORE;
    *(ushort4*)(row + j4)       = hi4;
    *(ushort4*)(row + 512 + j4) = lo4;
}

// ---------------- mma.sync bf16 GEMM: out[M,256] = tanh(Aexp @ Wb^T + bias) ----------------
// CTA 128x128, 8 warps (4x2), warp tile 32x64, K pipelined in 64-elem chunks.
__global__ __launch_bounds__(256, 1)
void sage_mma_gemm(const __nv_bfloat16* __restrict__ Aexp,
                   const __nv_bfloat16* __restrict__ Wb,
                   const float* __restrict__ bias,
                   float* __restrict__ out, int M) {
    extern __shared__ __align__(1024) char smem[];
    const uint32_t TILES = (smem_u32(smem) + 1023u) & ~1023u;

    const int tid  = threadIdx.x;
    const int wid  = tid >> 5;
    const int lane = tid & 31;
    const int wm   = wid & 3;           // 4 warps along M
    const int wn   = wid >> 2;          // 2 warps along N
    const int row0 = blockIdx.x * BM;
    const int col0 = blockIdx.y * BN;

    // cp.async mappings: 1024 16B transfers per tile, 4 per thread
    const int ld_r = tid >> 3;          // row 0..31 base (x4 strided by 32)
    const int ld_q = tid & 7;           // 16B quad within 128B row

    // ldmatrix per-lane byte offsets within tile (before k-step advance + SWZ)
    uint32_t aPart[2], bPart[4];
    {
        int r  = (lane & 15);
        int hb = (lane >> 4) * 16;
        #pragma unroll
        for (int mi = 0; mi < 2; mi++)
            aPart[mi] = (uint32_t)((wm * 32 + mi * 16 + r) * 128 + hb);
        #pragma unroll
        for (int g = 0; g < 4; g++)
            bPart[g] = (uint32_t)((wn * 64 + g * 16 + r) * 128 + hb);
    }

    float acc[2][8][4];
    #pragma unroll
    for (int mi = 0; mi < 2; mi++)
        #pragma unroll
        for (int ni = 0; ni < 8; ni++)
            #pragma unroll
            for (int t = 0; t < 4; t++) acc[mi][ni][t] = 0.0f;

    auto load_chunk = [&](int c) {
        const int s  = c % STAGES;
        const int kb = c * KC;                       // expanded-K offset
        const int ka = (kb < 512) ? kb : kb - 512;   // dedup'd A offset
        const uint32_t sA = TILES + s * STAGE_BYTES;
        const uint32_t sB = sA + BM * 128;
        #pragma unroll
        for (int i = 0; i < 4; i++) {
            int m = ld_r + i * 32;
            int gr = row0 + m; if (gr > M - 1) gr = M - 1;
            cp_async16(sA + SWZ(m * 128 + ld_q * 16),
                       Aexp + (size_t)gr * KSTORE + ka + ld_q * 8);
        }
        #pragma unroll
        for (int i = 0; i < 4; i++) {
            int n = ld_r + i * 32;
            cp_async16(sB + SWZ(n * 128 + ld_q * 16),
                       Wb + (size_t)(col0 + n) * KEXP + kb + ld_q * 8);
        }
        CP_COMMIT();
    };

    load_chunk(0);
    load_chunk(1);

    #pragma unroll 1
    for (int c = 0; c < NCHUNK; c++) {
        if (c == NCHUNK - 1) { CP_WAIT(0); } else { CP_WAIT(1); }
        __syncthreads();
        if (c + 2 < NCHUNK) load_chunk(c + 2);

        const uint32_t sA = TILES + (c % STAGES) * STAGE_BYTES;
        const uint32_t sB = sA + BM * 128;

        #pragma unroll
        for (int ks = 0; ks < 4; ks++) {
            const uint32_t kadv = ks * 32;
            uint32_t a[2][4];
            #pragma unroll
            for (int mi = 0; mi < 2; mi++)
                ldsm_x4(a[mi][0], a[mi][1], a[mi][2], a[mi][3],
                        sA + SWZ(aPart[mi] + kadv));
            uint32_t b[8][2];
            #pragma unroll
            for (int g = 0; g < 4; g++) {
                uint32_t r0, r1, r2, r3;
                ldsm_x4(r0, r1, r2, r3, sB + SWZ(bPart[g] + kadv));
                b[2*g][0] = r0;  b[2*g+1][0] = r1;   // n-tile0 b0, n-tile1 b0
                b[2*g][1] = r2;  b[2*g+1][1] = r3;   // n-tile0 b1, n-tile1 b1
            }
            #pragma unroll
            for (int mi = 0; mi < 2; mi++)
                #pragma unroll
                for (int ni = 0; ni < 8; ni++)
                    mma_bf16(acc[mi][ni],
                             a[mi][0], a[mi][1], a[mi][2], a[mi][3],
                             b[ni][0], b[ni][1]);
        }
    }

    // epilogue: bias + tanh
    const int rbase = row0 + wm * 32 + (lane >> 2);
    const int cbase = col0 + wn * 64 + 2 * (lane & 3);
    #pragma unroll
    for (int ni = 0; ni < 8; ni++) {
        const int col = cbase + ni * 8;
        const float2 bv = *(const float2*)(bias + col);
        #pragma unroll
        for (int mi = 0; mi < 2; mi++) {
            int r = rbase + mi * 16;
            if (r < M) {
                float2 o;
                o.x = tanhf(acc[mi][ni][0] + bv.x);
                o.y = tanhf(acc[mi][ni][1] + bv.y);
                *(float2*)(out + (size_t)r * D + col) = o;
            }
            if (r + 8 < M) {
                float2 o;
                o.x = tanhf(acc[mi][ni][2] + bv.x);
                o.y = tanhf(acc[mi][ni][3] + bv.y);
                *(float2*)(out + (size_t)(r + 8) * D + col) = o;
            }
        }
    }
}

// ---------------- launch ----------------
extern "C" void kernel_launch(void* const* d_in, const int* in_sizes, int n_in,
                              void* d_out, int out_size) {
    const float* nodes = (const float*)d_in[0];
    const float* Wl1   = (const float*)d_in[1];
    const float* b1    = (const float*)d_in[2];
    const float* Wr1   = (const float*)d_in[3];
    const float* Wl2   = (const float*)d_in[4];
    const float* b2    = (const float*)d_in[5];
    const float* Wr2   = (const float*)d_in[6];
    const int*   src1  = (const int*)d_in[7];
    const int*   dst1  = (const int*)d_in[8];
    const int*   src2  = (const int*)d_in[9];
    const int*   dst2  = (const int*)d_in[10];
    const int E1 = in_sizes[7];
    const int E2 = in_sizes[9];

    float *p_agg1, *p_cnt1, *p_inv1, *p_h1, *p_agg2, *p_cnt2, *p_inv2;
    __nv_bfloat16 *p_Aexp, *p_Wb1, *p_Wb2;
    cudaGetSymbolAddress((void**)&p_agg1, g_agg1);
    cudaGetSymbolAddress((void**)&p_cnt1, g_cnt1);
    cudaGetSymbolAddress((void**)&p_inv1, g_inv1);
    cudaGetSymbolAddress((void**)&p_h1,   g_h1);
    cudaGetSymbolAddress((void**)&p_agg2, g_agg2);
    cudaGetSymbolAddress((void**)&p_cnt2, g_cnt2);
    cudaGetSymbolAddress((void**)&p_inv2, g_inv2);
    cudaGetSymbolAddress((void**)&p_Aexp, g_Aexp);
    cudaGetSymbolAddress((void**)&p_Wb1,  g_Wb1);
    cudaGetSymbolAddress((void**)&p_Wb2,  g_Wb2);

    cudaFuncSetAttribute(sage_mma_gemm, cudaFuncAttributeMaxDynamicSharedMemorySize,
                         SMEM_BYTES);

    cudaMemsetAsync(p_agg1, 0, sizeof(float) * (size_t)N1C * D);
    cudaMemsetAsync(p_cnt1, 0, sizeof(float) * N1C);
    cudaMemsetAsync(p_agg2, 0, sizeof(float) * (size_t)N2C * D);
    cudaMemsetAsync(p_cnt2, 0, sizeof(float) * N2C);

    wprep_kernel<<<(D * 512 + 255) / 256, 256>>>(Wl1, Wr1, p_Wb1);
    wprep_kernel<<<(D * 512 + 255) / 256, 256>>>(Wl2, Wr2, p_Wb2);

    // ---- layer 1 ----
    {
        long long threads = (long long)E1 * 32;
        int blocks = (int)((threads + 255) / 256);
        scatter_kernel<<<blocks, 256>>>(nodes, src1, dst1, E1, p_agg1, p_cnt1);
    }
    inv_kernel<<<(N1C + 255) / 256, 256>>>(p_cnt1, p_inv1, N1C);
    aprep_kernel<<<(N1C * 128 + 255) / 256, 256>>>(p_agg1, p_inv1, nodes, p_Aexp, N1C);
    {
        dim3 grid((N1C + BM - 1) / BM, D / BN);
        sage_mma_gemm<<<grid, 256, SMEM_BYTES>>>(p_Aexp, p_Wb1, b1, p_h1, N1C);
    }

    // ---- layer 2 ----
    {
        long long threads = (long long)E2 * 32;
        int blocks = (int)((threads + 255) / 256);
        scatter_kernel<<<blocks, 256>>>(p_h1, src2, dst2, E2, p_agg2, p_cnt2);
    }
    inv_kernel<<<(N2C + 255) / 256, 256>>>(p_cnt2, p_inv2, N2C);
    aprep_kernel<<<(N2C * 128 + 255) / 256, 256>>>(p_agg2, p_inv2, p_h1, p_Aexp, N2C);
    {
        dim3 grid((N2C + BM - 1) / BM, D / BN);
        sage_mma_gemm<<<grid, 256, SMEM_BYTES>>>(p_Aexp, p_Wb2, b2, (float*)d_out, N2C);
    }
}

// round 8
// speedup vs baseline: 1.5396x; 1.0680x over previous
#include <cuda_runtime.h>
#include <cuda_bf16.h>
#include <math.h>
#include <stdint.h>

#define D      256
#define N1C    40000
#define N2C    8000
#define E1MAX  1000000
#define KEXP   1536          // expanded K:  [Ah|Ah|Al] x [Wh;Wl;Wh]
#define KSTORE 1024          // Aexp stored dedup'd: [Ah|Al]
#define BM     128
#define BN     128
#define KC     64
#define NCHUNK 24            // 1536/64
#define STAGES 3
#define STAGE_BYTES (BM*128 + BN*128)
#define SMEM_BYTES  (STAGES*STAGE_BYTES + 1024)

// ---------------- scratch ----------------
__device__ float g_h1[(size_t)N1C * D];
__device__ __nv_bfloat16 g_Aexp[(size_t)N1C * KSTORE];   // 81.9 MB (reused layer 2)
__device__ __nv_bfloat16 g_Wb1[(size_t)D * KEXP];
__device__ __nv_bfloat16 g_Wb2[(size_t)D * KEXP];
__device__ int g_hist[N1C];
__device__ int g_off[N1C + 1];
__device__ int g_cur[N1C];
__device__ int g_ssrc[E1MAX];

// ---------------- helpers ----------------
__device__ __forceinline__ uint32_t smem_u32(const void* p) {
    uint32_t a;
    asm("{ .reg .u64 t; cvta.to.shared.u64 t, %1; cvt.u32.u64 %0, t; }"
        : "=r"(a) : "l"(p));
    return a;
}
#define SWZ(o) ((o) ^ (((o) >> 3) & 0x70))

__device__ __forceinline__ void cp_async16(uint32_t dst, const void* src) {
    asm volatile("cp.async.cg.shared.global [%0], [%1], 16;" :: "r"(dst), "l"(src));
}
#define CP_COMMIT()  asm volatile("cp.async.commit_group;")
#define CP_WAIT(n)   asm volatile("cp.async.wait_group %0;" :: "n"(n))

__device__ __forceinline__ void ldsm_x4(uint32_t& r0, uint32_t& r1,
                                        uint32_t& r2, uint32_t& r3, uint32_t addr) {
    asm volatile("ldmatrix.sync.aligned.m8n8.x4.shared.b16 {%0,%1,%2,%3}, [%4];"
                 : "=r"(r0), "=r"(r1), "=r"(r2), "=r"(r3) : "r"(addr));
}
__device__ __forceinline__ void mma_bf16(float* c,
        uint32_t a0, uint32_t a1, uint32_t a2, uint32_t a3,
        uint32_t b0, uint32_t b1) {
    asm volatile(
        "mma.sync.aligned.m16n8k16.row.col.f32.bf16.bf16.f32 "
        "{%0,%1,%2,%3}, {%4,%5,%6,%7}, {%8,%9}, {%0,%1,%2,%3};"
        : "+f"(c[0]), "+f"(c[1]), "+f"(c[2]), "+f"(c[3])
        : "r"(a0), "r"(a1), "r"(a2), "r"(a3), "r"(b0), "r"(b1));
}

// ---------------- sort-by-dst pipeline ----------------
__global__ void hist_kernel(const int* __restrict__ dst, int E, int* __restrict__ hist) {
    int i = blockIdx.x * blockDim.x + threadIdx.x;
    if (i < E) atomicAdd(hist + dst[i], 1);
}

__global__ void scan_kernel(const int* __restrict__ hist, int* __restrict__ off,
                            int* __restrict__ cur, int n, int E) {
    __shared__ int part[1024];
    const int t = threadIdx.x;
    const int chunk = (n + 1023) / 1024;
    int b0 = t * chunk;
    int b1 = b0 + chunk; if (b1 > n) b1 = n;
    if (b0 > n) b0 = n;
    int s = 0;
    for (int i = b0; i < b1; i++) s += hist[i];
    part[t] = s;
    __syncthreads();
    #pragma unroll
    for (int d = 1; d < 1024; d <<= 1) {
        int v = (t >= d) ? part[t - d] : 0;
        __syncthreads();
        part[t] += v;
        __syncthreads();
    }
    int run = (t > 0) ? part[t - 1] : 0;
    for (int i = b0; i < b1; i++) {
        off[i] = run;
        cur[i] = run;
        run += hist[i];
    }
    if (t == 0) off[n] = E;
}

__global__ void bin_kernel(const int* __restrict__ src, const int* __restrict__ dst,
                           int E, int* __restrict__ cur, int* __restrict__ ssrc) {
    int i = blockIdx.x * blockDim.x + threadIdx.x;
    if (i >= E) return;
    int p = atomicAdd(cur + dst[i], 1);
    ssrc[p] = src[i];
}

// ---------------- fused aggregation + mean + bf16-split prep ----------------
// warp per dst node: mean over segment, load x_tgt row, write Aexp row:
// [0:256)=hi(mean) [256:512)=hi(x) [512:768)=lo(mean) [768:1024)=lo(x)
__device__ __forceinline__ void split4(float4 v, ushort4& hi, ushort4& lo) {
    float f[4] = {v.x, v.y, v.z, v.w};
    unsigned short* hp = &hi.x;
    unsigned short* lp = &lo.x;
    #pragma unroll
    for (int t = 0; t < 4; t++) {
        __nv_bfloat16 h = __float2bfloat16(f[t]);
        __nv_bfloat16 l = __float2bfloat16(f[t] - __bfloat162float(h));
        hp[t] = *(unsigned short*)&h;
        lp[t] = *(unsigned short*)&l;
    }
}
__device__ __forceinline__ void acc4(float4& a, float4 v) {
    a.x += v.x; a.y += v.y; a.z += v.z; a.w += v.w;
}

__global__ void agg_prep_kernel(const float* __restrict__ x,
                                const int* __restrict__ off,
                                const int* __restrict__ ssrc,
                                __nv_bfloat16* __restrict__ Aexp, int n) {
    const int d = (blockIdx.x * blockDim.x + threadIdx.x) >> 5;
    const int lane = threadIdx.x & 31;
    if (d >= n) return;
    const int beg = __ldg(off + d);
    const int end = __ldg(off + d + 1);

    float4 a0 = make_float4(0, 0, 0, 0), a1 = make_float4(0, 0, 0, 0);
    int e = beg;
    // 4-edge unroll: 8 outstanding LDG.128 per lane
    for (; e + 4 <= end; e += 4) {
        int s0 = __ldg(ssrc + e + 0);
        int s1 = __ldg(ssrc + e + 1);
        int s2 = __ldg(ssrc + e + 2);
        int s3 = __ldg(ssrc + e + 3);
        const float4* p0 = (const float4*)(x + (size_t)s0 * D);
        const float4* p1 = (const float4*)(x + (size_t)s1 * D);
        const float4* p2 = (const float4*)(x + (size_t)s2 * D);
        const float4* p3 = (const float4*)(x + (size_t)s3 * D);
        float4 u00 = __ldg(p0 + lane),      u01 = __ldg(p0 + lane + 32);
        float4 u10 = __ldg(p1 + lane),      u11 = __ldg(p1 + lane + 32);
        float4 u20 = __ldg(p2 + lane),      u21 = __ldg(p2 + lane + 32);
        float4 u30 = __ldg(p3 + lane),      u31 = __ldg(p3 + lane + 32);
        acc4(a0, u00); acc4(a1, u01);
        acc4(a0, u10); acc4(a1, u11);
        acc4(a0, u20); acc4(a1, u21);
        acc4(a0, u30); acc4(a1, u31);
    }
    for (; e < end; e++) {
        int s = __ldg(ssrc + e);
        const float4* p = (const float4*)(x + (size_t)s * D);
        acc4(a0, __ldg(p + lane));
        acc4(a1, __ldg(p + lane + 32));
    }

    const float inv = 1.0f / fmaxf((float)(end - beg), 1.0f);
    a0.x *= inv; a0.y *= inv; a0.z *= inv; a0.w *= inv;
    a1.x *= inv; a1.y *= inv; a1.z *= inv; a1.w *= inv;

    // x_tgt row (same table: x_tgt = x[:n])
    const float4* pt = (const float4*)(x + (size_t)d * D);
    float4 t0 = __ldg(pt + lane), t1 = __ldg(pt + lane + 32);

    ushort4 h, l;
    __nv_bfloat16* row = Aexp + (size_t)d * KSTORE;
    split4(a0, h, l);
    *(ushort4*)(row +   0 + 4 * lane) = h;  *(ushort4*)(row + 512 + 4 * lane) = l;
    split4(a1, h, l);
    *(ushort4*)(row + 128 + 4 * lane) = h;  *(ushort4*)(row + 640 + 4 * lane) = l;
    split4(t0, h, l);
    *(ushort4*)(row + 256 + 4 * lane) = h;  *(ushort4*)(row + 768 + 4 * lane) = l;
    split4(t1, h, l);
    *(ushort4*)(row + 384 + 4 * lane) = h;  *(ushort4*)(row + 896 + 4 * lane) = l;
}

// ---------------- weight prep ----------------
__global__ void wprep_kernel(const float* __restrict__ Wl, const float* __restrict__ Wr,
                             __nv_bfloat16* __restrict__ Wb) {
    int i = blockIdx.x * blockDim.x + threadIdx.x;
    if (i >= D * 512) return;
    int n = i / 512, k = i % 512;
    float w = (k < D) ? Wl[n * D + k] : Wr[n * D + (k - D)];
    __nv_bfloat16 hi = __float2bfloat16(w);
    __nv_bfloat16 lo = __float2bfloat16(w - __bfloat162float(hi));
    __nv_bfloat16* row = Wb + (size_t)n * KEXP;
    row[k]        = hi;
    row[512 + k]  = lo;
    row[1024 + k] = hi;
}

// ---------------- mma.sync bf16 GEMM (R7-proven, unchanged) ----------------
__global__ __launch_bounds__(256, 1)
void sage_mma_gemm(const __nv_bfloat16* __restrict__ Aexp,
                   const __nv_bfloat16* __restrict__ Wb,
                   const float* __restrict__ bias,
                   float* __restrict__ out, int M) {
    extern __shared__ __align__(1024) char smem[];
    const uint32_t TILES = (smem_u32(smem) + 1023u) & ~1023u;

    const int tid  = threadIdx.x;
    const int wid  = tid >> 5;
    const int lane = tid & 31;
    const int wm   = wid & 3;
    const int wn   = wid >> 2;
    const int row0 = blockIdx.x * BM;
    const int col0 = blockIdx.y * BN;

    const int ld_r = tid >> 3;
    const int ld_q = tid & 7;

    uint32_t aPart[2], bPart[4];
    {
        int r  = (lane & 15);
        int hb = (lane >> 4) * 16;
        #pragma unroll
        for (int mi = 0; mi < 2; mi++)
            aPart[mi] = (uint32_t)((wm * 32 + mi * 16 + r) * 128 + hb);
        #pragma unroll
        for (int g = 0; g < 4; g++)
            bPart[g] = (uint32_t)((wn * 64 + g * 16 + r) * 128 + hb);
    }

    float acc[2][8][4];
    #pragma unroll
    for (int mi = 0; mi < 2; mi++)
        #pragma unroll
        for (int ni = 0; ni < 8; ni++)
            #pragma unroll
            for (int t = 0; t < 4; t++) acc[mi][ni][t] = 0.0f;

    auto load_chunk = [&](int c) {
        const int s  = c % STAGES;
        const int kb = c * KC;
        const int ka = (kb < 512) ? kb : kb - 512;
        const uint32_t sA = TILES + s * STAGE_BYTES;
        const uint32_t sB = sA + BM * 128;
        #pragma unroll
        for (int i = 0; i < 4; i++) {
            int m = ld_r + i * 32;
            int gr = row0 + m; if (gr > M - 1) gr = M - 1;
            cp_async16(sA + SWZ(m * 128 + ld_q * 16),
                       Aexp + (size_t)gr * KSTORE + ka + ld_q * 8);
        }
        #pragma unroll
        for (int i = 0; i < 4; i++) {
            int n = ld_r + i * 32;
            cp_async16(sB + SWZ(n * 128 + ld_q * 16),
                       Wb + (size_t)(col0 + n) * KEXP + kb + ld_q * 8);
        }
        CP_COMMIT();
    };

    load_chunk(0);
    load_chunk(1);

    #pragma unroll 1
    for (int c = 0; c < NCHUNK; c++) {
        if (c == NCHUNK - 1) { CP_WAIT(0); } else { CP_WAIT(1); }
        __syncthreads();
        if (c + 2 < NCHUNK) load_chunk(c + 2);

        const uint32_t sA = TILES + (c % STAGES) * STAGE_BYTES;
        const uint32_t sB = sA + BM * 128;

        #pragma unroll
        for (int ks = 0; ks < 4; ks++) {
            const uint32_t kadv = ks * 32;
            uint32_t a[2][4];
            #pragma unroll
            for (int mi = 0; mi < 2; mi++)
                ldsm_x4(a[mi][0], a[mi][1], a[mi][2], a[mi][3],
                        sA + SWZ(aPart[mi] + kadv));
            uint32_t b[8][2];
            #pragma unroll
            for (int g = 0; g < 4; g++) {
                uint32_t r0, r1, r2, r3;
                ldsm_x4(r0, r1, r2, r3, sB + SWZ(bPart[g] + kadv));
                b[2*g][0] = r0;  b[2*g+1][0] = r1;
                b[2*g][1] = r2;  b[2*g+1][1] = r3;
            }
            #pragma unroll
            for (int mi = 0; mi < 2; mi++)
                #pragma unroll
                for (int ni = 0; ni < 8; ni++)
                    mma_bf16(acc[mi][ni],
                             a[mi][0], a[mi][1], a[mi][2], a[mi][3],
                             b[ni][0], b[ni][1]);
        }
    }

    const int rbase = row0 + wm * 32 + (lane >> 2);
    const int cbase = col0 + wn * 64 + 2 * (lane & 3);
    #pragma unroll
    for (int ni = 0; ni < 8; ni++) {
        const int col = cbase + ni * 8;
        const float2 bv = *(const float2*)(bias + col);
        #pragma unroll
        for (int mi = 0; mi < 2; mi++) {
            int r = rbase + mi * 16;
            if (r < M) {
                float2 o;
                o.x = tanhf(acc[mi][ni][0] + bv.x);
                o.y = tanhf(acc[mi][ni][1] + bv.y);
                *(float2*)(out + (size_t)r * D + col) = o;
            }
            if (r + 8 < M) {
                float2 o;
                o.x = tanhf(acc[mi][ni][2] + bv.x);
                o.y = tanhf(acc[mi][ni][3] + bv.y);
                *(float2*)(out + (size_t)(r + 8) * D + col) = o;
            }
        }
    }
}

// ---------------- launch ----------------
extern "C" void kernel_launch(void* const* d_in, const int* in_sizes, int n_in,
                              void* d_out, int out_size) {
    const float* nodes = (const float*)d_in[0];
    const float* Wl1   = (const float*)d_in[1];
    const float* b1    = (const float*)d_in[2];
    const float* Wr1   = (const float*)d_in[3];
    const float* Wl2   = (const float*)d_in[4];
    const float* b2    = (const float*)d_in[5];
    const float* Wr2   = (const float*)d_in[6];
    const int*   src1  = (const int*)d_in[7];
    const int*   dst1  = (const int*)d_in[8];
    const int*   src2  = (const int*)d_in[9];
    const int*   dst2  = (const int*)d_in[10];
    const int E1 = in_sizes[7];
    const int E2 = in_sizes[9];

    float *p_h1;
    __nv_bfloat16 *p_Aexp, *p_Wb1, *p_Wb2;
    int *p_hist, *p_off, *p_cur, *p_ssrc;
    cudaGetSymbolAddress((void**)&p_h1,   g_h1);
    cudaGetSymbolAddress((void**)&p_Aexp, g_Aexp);
    cudaGetSymbolAddress((void**)&p_Wb1,  g_Wb1);
    cudaGetSymbolAddress((void**)&p_Wb2,  g_Wb2);
    cudaGetSymbolAddress((void**)&p_hist, g_hist);
    cudaGetSymbolAddress((void**)&p_off,  g_off);
    cudaGetSymbolAddress((void**)&p_cur,  g_cur);
    cudaGetSymbolAddress((void**)&p_ssrc, g_ssrc);

    cudaFuncSetAttribute(sage_mma_gemm, cudaFuncAttributeMaxDynamicSharedMemorySize,
                         SMEM_BYTES);

    wprep_kernel<<<(D * 512 + 255) / 256, 256>>>(Wl1, Wr1, p_Wb1);
    wprep_kernel<<<(D * 512 + 255) / 256, 256>>>(Wl2, Wr2, p_Wb2);

    // ---- layer 1 ----
    cudaMemsetAsync(p_hist, 0, sizeof(int) * N1C);
    hist_kernel<<<(E1 + 255) / 256, 256>>>(dst1, E1, p_hist);
    scan_kernel<<<1, 1024>>>(p_hist, p_off, p_cur, N1C, E1);
    bin_kernel<<<(E1 + 255) / 256, 256>>>(src1, dst1, E1, p_cur, p_ssrc);
    agg_prep_kernel<<<(N1C * 32 + 255) / 256, 256>>>(nodes, p_off, p_ssrc, p_Aexp, N1C);
    {
        dim3 grid((N1C + BM - 1) / BM, D / BN);
        sage_mma_gemm<<<grid, 256, SMEM_BYTES>>>(p_Aexp, p_Wb1, b1, p_h1, N1C);
    }

    // ---- layer 2 ----
    cudaMemsetAsync(p_hist, 0, sizeof(int) * N2C);
    hist_kernel<<<(E2 + 255) / 256, 256>>>(dst2, E2, p_hist);
    scan_kernel<<<1, 1024>>>(p_hist, p_off, p_cur, N2C, E2);
    bin_kernel<<<(E2 + 255) / 256, 256>>>(src2, dst2, E2, p_cur, p_ssrc);
    agg_prep_kernel<<<(N2C * 32 + 255) / 256, 256>>>(p_h1, p_off, p_ssrc, p_Aexp, N2C);
    {
        dim3 grid((N2C + BM - 1) / BM, D / BN);
        sage_mma_gemm<<<grid, 256, SMEM_BYTES>>>(p_Aexp, p_Wb2, b2, (float*)d_out, N2C);
    }
}